// round 6
// baseline (speedup 1.0000x reference)
#include <cuda_runtime.h>

// Fixed problem shapes
#define BSZ  4
#define TT   1024
#define DDIM 512
#define HH   8
#define DH   64
#define MROWS (BSZ*TT)   // 4096
#define NBH   (BSZ*HH)   // 32
#define INV_TAU 10.0f

// Scratch (device globals: allocation-free)
__device__ __align__(128) float g_qkv[3][MROWS][DDIM];   // 25 MB: q,k,v post-softmax
__device__ __align__(128) float g_S[NBH][TT][TT];        // 134 MB: scores -> scan
__device__ __align__(128) float g_O[NBH][TT][DH];        // 8 MB: attention output

// ---------------------------------------------------------------------------
// K1: QKV projections WITH fused per-head softmax(x/tau) epilogue.
// 128x128 tile, BK=8, 8x8 per thread, 256 threads. grid (4, 32, 3).
// ---------------------------------------------------------------------------
__global__ __launch_bounds__(256) void k_qkv(const float* __restrict__ X,
                                             const float* __restrict__ Wq,
                                             const float* __restrict__ Wk,
                                             const float* __restrict__ Wv) {
    const float* W = (blockIdx.z == 0) ? Wq : ((blockIdx.z == 1) ? Wk : Wv);
    float* Out = &g_qkv[blockIdx.z][0][0];
    __shared__ float As[8][128];
    __shared__ float Bs[8][128];
    int tid = threadIdx.x;
    int m0 = blockIdx.y * 128, n0 = blockIdx.x * 128;
    int arow = tid >> 1, acol = (tid & 1) * 4;
    int brow = tid >> 5, bcol = (tid & 31) * 4;
    int tx = tid & 15, ty = tid >> 4;
    float acc[8][8];
#pragma unroll
    for (int r = 0; r < 8; r++)
#pragma unroll
        for (int c = 0; c < 8; c++) acc[r][c] = 0.f;

    for (int k0 = 0; k0 < DDIM; k0 += 8) {
        float4 av = *(const float4*)&X[(m0 + arow) * DDIM + k0 + acol];
        float4 bv = *(const float4*)&W[(k0 + brow) * DDIM + n0 + bcol];
        __syncthreads();
        As[acol + 0][arow] = av.x; As[acol + 1][arow] = av.y;
        As[acol + 2][arow] = av.z; As[acol + 3][arow] = av.w;
        *(float4*)&Bs[brow][bcol] = bv;
        __syncthreads();
#pragma unroll
        for (int k = 0; k < 8; k++) {
            float a[8], b[8];
            *(float4*)&a[0] = *(const float4*)&As[k][ty * 8];
            *(float4*)&a[4] = *(const float4*)&As[k][ty * 8 + 4];
            *(float4*)&b[0] = *(const float4*)&Bs[k][tx * 8];
            *(float4*)&b[4] = *(const float4*)&Bs[k][tx * 8 + 4];
#pragma unroll
            for (int r = 0; r < 8; r++)
#pragma unroll
                for (int c = 0; c < 8; c++) acc[r][c] += a[r] * b[c];
        }
    }
    // fused softmax over each head's 64 cols (8 cols local x 8 lanes)
#pragma unroll
    for (int r = 0; r < 8; r++) {
        float mx = acc[r][0];
#pragma unroll
        for (int c = 1; c < 8; c++) mx = fmaxf(mx, acc[r][c]);
#pragma unroll
        for (int o = 4; o > 0; o >>= 1) mx = fmaxf(mx, __shfl_xor_sync(0xffffffffu, mx, o));
        float s = 0.f;
#pragma unroll
        for (int c = 0; c < 8; c++) {
            acc[r][c] = __expf((acc[r][c] - mx) * INV_TAU);
            s += acc[r][c];
        }
#pragma unroll
        for (int o = 4; o > 0; o >>= 1) s += __shfl_xor_sync(0xffffffffu, s, o);
        float inv = 1.f / s;
#pragma unroll
        for (int c = 0; c < 8; c++) acc[r][c] *= inv;
    }
#pragma unroll
    for (int r = 0; r < 8; r++) {
        int row = m0 + ty * 8 + r;
        *(float4*)&Out[row * DDIM + n0 + tx * 8]     = *(float4*)&acc[r][0];
        *(float4*)&Out[row * DDIM + n0 + tx * 8 + 4] = *(float4*)&acc[r][4];
    }
}

// ---------------------------------------------------------------------------
// K3: S = q_sm·k_smT, causal 128x128 tiles, BK=32, 8x8/thread.
// grid (8, 8, 32), block 256.
// ---------------------------------------------------------------------------
__global__ __launch_bounds__(256) void k_score() {
    int jt = blockIdx.x, it = blockIdx.y, bh = blockIdx.z;
    if (jt > it) return;
    int b = bh >> 3, h = bh & 7;
    const float* Q  = &g_qkv[0][b * TT][h * DH];
    const float* Kp = &g_qkv[1][b * TT][h * DH];
    __shared__ float Qs[32][132];
    __shared__ float Ks[32][132];
    int tid = threadIdx.x;
    int tx = tid & 15, ty = tid >> 4;
    float acc[8][8];
#pragma unroll
    for (int r = 0; r < 8; r++)
#pragma unroll
        for (int c = 0; c < 8; c++) acc[r][c] = 0.f;

    for (int k0 = 0; k0 < DH; k0 += 32) {
        __syncthreads();
#pragma unroll
        for (int l = 0; l < 4; l++) {
            int idx = tid + l * 256;
            int row = idx >> 3, cg = (idx & 7) * 4;
            float4 q4 = *(const float4*)&Q[(it * 128 + row) * DDIM + k0 + cg];
            float4 k4 = *(const float4*)&Kp[(jt * 128 + row) * DDIM + k0 + cg];
            Qs[cg + 0][row] = q4.x; Qs[cg + 1][row] = q4.y;
            Qs[cg + 2][row] = q4.z; Qs[cg + 3][row] = q4.w;
            Ks[cg + 0][row] = k4.x; Ks[cg + 1][row] = k4.y;
            Ks[cg + 2][row] = k4.z; Ks[cg + 3][row] = k4.w;
        }
        __syncthreads();
#pragma unroll
        for (int k = 0; k < 32; k++) {
            float a[8], bb[8];
            *(float4*)&a[0]  = *(const float4*)&Qs[k][ty * 8];
            *(float4*)&a[4]  = *(const float4*)&Qs[k][ty * 8 + 4];
            *(float4*)&bb[0] = *(const float4*)&Ks[k][tx * 8];
            *(float4*)&bb[4] = *(const float4*)&Ks[k][tx * 8 + 4];
#pragma unroll
            for (int r = 0; r < 8; r++)
#pragma unroll
                for (int c = 0; c < 8; c++) acc[r][c] += a[r] * bb[c];
        }
    }
    float* Sp = &g_S[bh][0][0];
#pragma unroll
    for (int r = 0; r < 8; r++) {
        int row = it * 128 + ty * 8 + r;
        *(float4*)&Sp[row * TT + jt * 128 + tx * 8]     = *(float4*)&acc[r][0];
        *(float4*)&Sp[row * TT + jt * 128 + tx * 8 + 4] = *(float4*)&acc[r][4];
    }
}

// ---------------------------------------------------------------------------
// K4: per-subdiagonal scan, in place on g_S. A/B double-buffered 32-row
// blocks. grid (8, 32), block 128.
// ---------------------------------------------------------------------------
#define SPF 32
__global__ __launch_bounds__(128) void k_scan() {
    int bh = blockIdx.y;
    int dbase = blockIdx.x * 128;
    int d = dbase + threadIdx.x;
    float* Sp = &g_S[bh][0][0];
    float bufA[SPF], bufB[SPF];
    float s = 0.f, m = 0.f;
#pragma unroll
    for (int p = 0; p < SPF; p++) {
        int i = dbase + p, j = i - d;
        bufA[p] = (j >= 0) ? Sp[i * TT + j] : 0.f;
    }
    for (int ib = dbase; ib < TT; ib += 2 * SPF) {
#pragma unroll
        for (int p = 0; p < SPF; p++) {
            int i = ib + SPF + p, j = i - d;
            bufB[p] = (i < TT && j >= 0) ? Sp[i * TT + j] : 0.f;
        }
#pragma unroll
        for (int p = 0; p < SPF; p++) {
            int i = ib + p;
            if (i >= d && i < TT) {
                float a = bufA[p];
                s += a;
                m = fmaxf(m, s * (1.f - a));
                Sp[i * TT + (i - d)] = s - m;
            }
        }
#pragma unroll
        for (int p = 0; p < SPF; p++) {
            int i = ib + 2 * SPF + p, j = i - d;
            bufA[p] = (i < TT && j >= 0) ? Sp[i * TT + j] : 0.f;
        }
#pragma unroll
        for (int p = 0; p < SPF; p++) {
            int i = ib + SPF + p;
            if (i >= d && i < TT) {
                float a = bufB[p];
                s += a;
                m = fmaxf(m, s * (1.f - a));
                Sp[i * TT + (i - d)] = s - m;
            }
        }
    }
}

// ---------------------------------------------------------------------------
// K5: fused causal softmax((scan + j/(i+1))/tau) + P@V, TWO-PASS.
// Block = 128 i-rows x 64 Dh, 256 threads, thread = 8 rows x 4 cols.
// Pass 1: row max straight from GMEM (registers only, one shfl-reduce total).
// Pass 2: exp with fixed max -> Ps smem -> MAC; ssum deferred to the end.
// grid (8, 32), dynamic smem 52224 B (Vs 64x68 + Ps 128x68).
// ---------------------------------------------------------------------------
__global__ __launch_bounds__(256) void k_pvsm() {
    extern __shared__ float sh[];
    float* Vs = sh;                 // [64][68]
    float* Ps = sh + 64 * 68;       // [128][68]
    int it = blockIdx.x, bh = blockIdx.y;
    int b = bh >> 3, h = bh & 7;
    const float* __restrict__ Sp = &g_S[bh][0][0];
    const float* __restrict__ V = &g_qkv[2][b * TT][h * DH];
    int tid = threadIdx.x;
    int tx = tid & 15, ty = tid >> 4;
    int i0 = it * 128;
    int nt = 2 * it + 2;            // number of 64-wide j tiles

    int gi[8];
    float invi[8], mx[8];
#pragma unroll
    for (int rr = 0; rr < 8; rr++) {
        gi[rr] = i0 + ty * 8 + rr;
        invi[rr] = 1.f / (float)(gi[rr] + 1);
        mx[rr] = -1e30f;
    }

    // ---- pass 1: row max ----
    for (int jt = 0; jt < nt; jt++) {
        int jb = jt * 64 + tx * 4;
#pragma unroll
        for (int rr = 0; rr < 8; rr++) {
            float4 s4 = *(const float4*)&Sp[gi[rr] * TT + jb];
            float l0 = (jb + 0 <= gi[rr]) ? s4.x + (float)(jb + 0) * invi[rr] : -1e30f;
            float l1 = (jb + 1 <= gi[rr]) ? s4.y + (float)(jb + 1) * invi[rr] : -1e30f;
            float l2 = (jb + 2 <= gi[rr]) ? s4.z + (float)(jb + 2) * invi[rr] : -1e30f;
            float l3 = (jb + 3 <= gi[rr]) ? s4.w + (float)(jb + 3) * invi[rr] : -1e30f;
            mx[rr] = fmaxf(mx[rr], fmaxf(fmaxf(l0, l1), fmaxf(l2, l3)));
        }
    }
#pragma unroll
    for (int rr = 0; rr < 8; rr++)
#pragma unroll
        for (int o = 8; o > 0; o >>= 1)
            mx[rr] = fmaxf(mx[rr], __shfl_xor_sync(0xffffffffu, mx[rr], o));

    // ---- pass 2: exp + PV ----
    float acc[8][4], ssum[8];
#pragma unroll
    for (int rr = 0; rr < 8; rr++) {
        ssum[rr] = 0.f;
#pragma unroll
        for (int c = 0; c < 4; c++) acc[rr][c] = 0.f;
    }

    for (int jt = 0; jt < nt; jt++) {
        int j0 = jt * 64;
        // cooperative V tile load (64 rows x 64 cols)
#pragma unroll
        for (int l = 0; l < 4; l++) {
            int row = ty + l * 16;
            *(float4*)&Vs[row * 68 + tx * 4] =
                *(const float4*)&V[(j0 + row) * DDIM + tx * 4];
        }
        // probs for this thread's 8 rows x 4 cols
#pragma unroll
        for (int rr = 0; rr < 8; rr++) {
            int jb = j0 + tx * 4;
            float4 s4 = *(const float4*)&Sp[gi[rr] * TT + jb];
            float p0 = (jb + 0 <= gi[rr]) ? __expf((s4.x + (float)(jb + 0) * invi[rr] - mx[rr]) * INV_TAU) : 0.f;
            float p1 = (jb + 1 <= gi[rr]) ? __expf((s4.y + (float)(jb + 1) * invi[rr] - mx[rr]) * INV_TAU) : 0.f;
            float p2 = (jb + 2 <= gi[rr]) ? __expf((s4.z + (float)(jb + 2) * invi[rr] - mx[rr]) * INV_TAU) : 0.f;
            float p3 = (jb + 3 <= gi[rr]) ? __expf((s4.w + (float)(jb + 3) * invi[rr] - mx[rr]) * INV_TAU) : 0.f;
            ssum[rr] += p0 + p1 + p2 + p3;
            float4 p4 = {p0, p1, p2, p3};
            *(float4*)&Ps[(ty * 8 + rr) * 68 + tx * 4] = p4;
        }
        __syncthreads();
        // MAC: acc[rr][c] += sum_k Ps[row][k] * Vs[k][col]
#pragma unroll 4
        for (int k4 = 0; k4 < 64; k4 += 4) {
            float4 b0 = *(float4*)&Vs[(k4 + 0) * 68 + tx * 4];
            float4 b1 = *(float4*)&Vs[(k4 + 1) * 68 + tx * 4];
            float4 b2 = *(float4*)&Vs[(k4 + 2) * 68 + tx * 4];
            float4 b3 = *(float4*)&Vs[(k4 + 3) * 68 + tx * 4];
#pragma unroll
            for (int rr = 0; rr < 8; rr++) {
                float4 a = *(float4*)&Ps[(ty * 8 + rr) * 68 + k4];
                acc[rr][0] += a.x * b0.x + a.y * b1.x + a.z * b2.x + a.w * b3.x;
                acc[rr][1] += a.x * b0.y + a.y * b1.y + a.z * b2.y + a.w * b3.y;
                acc[rr][2] += a.x * b0.z + a.y * b1.z + a.z * b2.z + a.w * b3.z;
                acc[rr][3] += a.x * b0.w + a.y * b1.w + a.z * b2.w + a.w * b3.w;
            }
        }
        __syncthreads();
    }
#pragma unroll
    for (int rr = 0; rr < 8; rr++) {
#pragma unroll
        for (int o = 8; o > 0; o >>= 1)
            ssum[rr] += __shfl_xor_sync(0xffffffffu, ssum[rr], o);
        float inv = 1.f / ssum[rr];
        float4 o4 = {acc[rr][0] * inv, acc[rr][1] * inv, acc[rr][2] * inv, acc[rr][3] * inv};
        *(float4*)&g_O[bh][gi[rr]][tx * 4] = o4;
    }
}

// ---------------------------------------------------------------------------
// K7: out[b,t,h*64+e] = sum_d O[bh][t][d] * wo[h*64+d][e]. K=64, N=64.
// grid (16, 32), block 256.
// ---------------------------------------------------------------------------
__global__ __launch_bounds__(256) void k_out(const float* __restrict__ wo,
                                             float* __restrict__ out) {
    int it = blockIdx.x, bh = blockIdx.y;
    int b = bh >> 3, h = bh & 7;
    __shared__ float Os[DH][68];
    __shared__ float Ws[DH][68];
    int tid = threadIdx.x;
    int lrow = tid >> 4, lcol = (tid & 15) * 4;
#pragma unroll
    for (int l = 0; l < 4; l++) {
        int row = lrow + l * 16;
        float4 o4 = *(const float4*)&g_O[bh][it * 64 + row][lcol];
        Os[lcol + 0][row] = o4.x; Os[lcol + 1][row] = o4.y;
        Os[lcol + 2][row] = o4.z; Os[lcol + 3][row] = o4.w;
        float4 w4 = *(const float4*)&wo[(h * 64 + row) * 64 + lcol];
        *(float4*)&Ws[row][lcol] = w4;
    }
    __syncthreads();
    int tx = tid & 15, ty = tid >> 4;
    float acc[4][4];
#pragma unroll
    for (int r = 0; r < 4; r++)
#pragma unroll
        for (int c = 0; c < 4; c++) acc[r][c] = 0.f;
#pragma unroll 8
    for (int k = 0; k < 64; k++) {
        float4 a4 = *(const float4*)&Os[k][ty * 4];
        float4 b4 = *(const float4*)&Ws[k][tx * 4];
        float a[4] = {a4.x, a4.y, a4.z, a4.w};
        float bb[4] = {b4.x, b4.y, b4.z, b4.w};
#pragma unroll
        for (int r = 0; r < 4; r++)
#pragma unroll
            for (int c = 0; c < 4; c++) acc[r][c] += a[r] * bb[c];
    }
#pragma unroll
    for (int r = 0; r < 4; r++) {
        int t = it * 64 + ty * 4 + r;
        float4 o4 = {acc[r][0], acc[r][1], acc[r][2], acc[r][3]};
        *(float4*)&out[(b * TT + t) * DDIM + h * 64 + tx * 4] = o4;
    }
}

// ---------------------------------------------------------------------------
extern "C" void kernel_launch(void* const* d_in, const int* in_sizes, int n_in,
                              void* d_out, int out_size) {
    const float* x  = (const float*)d_in[0];
    const float* wq = (const float*)d_in[1];
    const float* wk = (const float*)d_in[2];
    const float* wv = (const float*)d_in[3];
    const float* wo = (const float*)d_in[4];
    float* out = (float*)d_out;

    const int PVSM_SMEM = (64 * 68 + 128 * 68) * 4;  // 52224 B
    cudaFuncSetAttribute(k_pvsm, cudaFuncAttributeMaxDynamicSharedMemorySize, PVSM_SMEM);

    k_qkv<<<dim3(4, 32, 3), 256>>>(x, wq, wk, wv);
    k_score<<<dim3(8, 8, 32), 256>>>();
    k_scan<<<dim3(8, 32), 128>>>();
    k_pvsm<<<dim3(8, 32), 256, PVSM_SMEM>>>();
    k_out<<<dim3(16, 32), 256>>>(wo, out);
}

// round 7
// speedup vs baseline: 1.1047x; 1.1047x over previous
#include <cuda_runtime.h>

// Fixed problem shapes
#define BSZ  4
#define TT   1024
#define DDIM 512
#define HH   8
#define DH   64
#define MROWS (BSZ*TT)   // 4096
#define NBH   (BSZ*HH)   // 32
#define INV_TAU 10.0f

// Scratch (device globals: allocation-free)
__device__ __align__(128) float g_qkv[3][MROWS][DDIM];   // 25 MB: q,k,v post-softmax
__device__ __align__(128) float g_S[NBH][TT][TT];        // 134 MB: scores -> scan
__device__ __align__(128) float g_O[NBH][TT][DH];        // 8 MB: attention output

// ---------------------------------------------------------------------------
// K1: QKV projections WITH fused per-head softmax(x/tau) epilogue.
// 128x128 tile, BK=8, 8x8 per thread, 256 threads. grid (4, 32, 3).
// ---------------------------------------------------------------------------
__global__ __launch_bounds__(256) void k_qkv(const float* __restrict__ X,
                                             const float* __restrict__ Wq,
                                             const float* __restrict__ Wk,
                                             const float* __restrict__ Wv) {
    const float* W = (blockIdx.z == 0) ? Wq : ((blockIdx.z == 1) ? Wk : Wv);
    float* Out = &g_qkv[blockIdx.z][0][0];
    __shared__ float As[8][128];
    __shared__ float Bs[8][128];
    int tid = threadIdx.x;
    int m0 = blockIdx.y * 128, n0 = blockIdx.x * 128;
    int arow = tid >> 1, acol = (tid & 1) * 4;
    int brow = tid >> 5, bcol = (tid & 31) * 4;
    int tx = tid & 15, ty = tid >> 4;
    float acc[8][8];
#pragma unroll
    for (int r = 0; r < 8; r++)
#pragma unroll
        for (int c = 0; c < 8; c++) acc[r][c] = 0.f;

    for (int k0 = 0; k0 < DDIM; k0 += 8) {
        float4 av = *(const float4*)&X[(m0 + arow) * DDIM + k0 + acol];
        float4 bv = *(const float4*)&W[(k0 + brow) * DDIM + n0 + bcol];
        __syncthreads();
        As[acol + 0][arow] = av.x; As[acol + 1][arow] = av.y;
        As[acol + 2][arow] = av.z; As[acol + 3][arow] = av.w;
        *(float4*)&Bs[brow][bcol] = bv;
        __syncthreads();
#pragma unroll
        for (int k = 0; k < 8; k++) {
            float a[8], b[8];
            *(float4*)&a[0] = *(const float4*)&As[k][ty * 8];
            *(float4*)&a[4] = *(const float4*)&As[k][ty * 8 + 4];
            *(float4*)&b[0] = *(const float4*)&Bs[k][tx * 8];
            *(float4*)&b[4] = *(const float4*)&Bs[k][tx * 8 + 4];
#pragma unroll
            for (int r = 0; r < 8; r++)
#pragma unroll
                for (int c = 0; c < 8; c++) acc[r][c] += a[r] * b[c];
        }
    }
    // fused softmax over each head's 64 cols (8 cols local x 8 lanes)
#pragma unroll
    for (int r = 0; r < 8; r++) {
        float mx = acc[r][0];
#pragma unroll
        for (int c = 1; c < 8; c++) mx = fmaxf(mx, acc[r][c]);
#pragma unroll
        for (int o = 4; o > 0; o >>= 1) mx = fmaxf(mx, __shfl_xor_sync(0xffffffffu, mx, o));
        float s = 0.f;
#pragma unroll
        for (int c = 0; c < 8; c++) {
            acc[r][c] = __expf((acc[r][c] - mx) * INV_TAU);
            s += acc[r][c];
        }
#pragma unroll
        for (int o = 4; o > 0; o >>= 1) s += __shfl_xor_sync(0xffffffffu, s, o);
        float inv = 1.f / s;
#pragma unroll
        for (int c = 0; c < 8; c++) acc[r][c] *= inv;
    }
#pragma unroll
    for (int r = 0; r < 8; r++) {
        int row = m0 + ty * 8 + r;
        *(float4*)&Out[row * DDIM + n0 + tx * 8]     = *(float4*)&acc[r][0];
        *(float4*)&Out[row * DDIM + n0 + tx * 8 + 4] = *(float4*)&acc[r][4];
    }
}

// ---------------------------------------------------------------------------
// K3: S = q_sm·k_smT, causal 128x128 tiles, BK=32, 8x8/thread.
// grid (8, 8, 32), block 256.
// ---------------------------------------------------------------------------
__global__ __launch_bounds__(256) void k_score() {
    int jt = blockIdx.x, it = blockIdx.y, bh = blockIdx.z;
    if (jt > it) return;
    int b = bh >> 3, h = bh & 7;
    const float* Q  = &g_qkv[0][b * TT][h * DH];
    const float* Kp = &g_qkv[1][b * TT][h * DH];
    __shared__ float Qs[32][132];
    __shared__ float Ks[32][132];
    int tid = threadIdx.x;
    int tx = tid & 15, ty = tid >> 4;
    float acc[8][8];
#pragma unroll
    for (int r = 0; r < 8; r++)
#pragma unroll
        for (int c = 0; c < 8; c++) acc[r][c] = 0.f;

    for (int k0 = 0; k0 < DH; k0 += 32) {
        __syncthreads();
#pragma unroll
        for (int l = 0; l < 4; l++) {
            int idx = tid + l * 256;
            int row = idx >> 3, cg = (idx & 7) * 4;
            float4 q4 = *(const float4*)&Q[(it * 128 + row) * DDIM + k0 + cg];
            float4 k4 = *(const float4*)&Kp[(jt * 128 + row) * DDIM + k0 + cg];
            Qs[cg + 0][row] = q4.x; Qs[cg + 1][row] = q4.y;
            Qs[cg + 2][row] = q4.z; Qs[cg + 3][row] = q4.w;
            Ks[cg + 0][row] = k4.x; Ks[cg + 1][row] = k4.y;
            Ks[cg + 2][row] = k4.z; Ks[cg + 3][row] = k4.w;
        }
        __syncthreads();
#pragma unroll
        for (int k = 0; k < 32; k++) {
            float a[8], bb[8];
            *(float4*)&a[0]  = *(const float4*)&Qs[k][ty * 8];
            *(float4*)&a[4]  = *(const float4*)&Qs[k][ty * 8 + 4];
            *(float4*)&bb[0] = *(const float4*)&Ks[k][tx * 8];
            *(float4*)&bb[4] = *(const float4*)&Ks[k][tx * 8 + 4];
#pragma unroll
            for (int r = 0; r < 8; r++)
#pragma unroll
                for (int c = 0; c < 8; c++) acc[r][c] += a[r] * bb[c];
        }
    }
    float* Sp = &g_S[bh][0][0];
#pragma unroll
    for (int r = 0; r < 8; r++) {
        int row = it * 128 + ty * 8 + r;
        *(float4*)&Sp[row * TT + jt * 128 + tx * 8]     = *(float4*)&acc[r][0];
        *(float4*)&Sp[row * TT + jt * 128 + tx * 8 + 4] = *(float4*)&acc[r][4];
    }
}

// ---------------------------------------------------------------------------
// K4: per-subdiagonal scan, in place on g_S. A/B double-buffered 32-row
// blocks. grid (8, 32), block 128.
// ---------------------------------------------------------------------------
#define SPF 32
__global__ __launch_bounds__(128) void k_scan() {
    int bh = blockIdx.y;
    int dbase = blockIdx.x * 128;
    int d = dbase + threadIdx.x;
    float* Sp = &g_S[bh][0][0];
    float bufA[SPF], bufB[SPF];
    float s = 0.f, m = 0.f;
#pragma unroll
    for (int p = 0; p < SPF; p++) {
        int i = dbase + p, j = i - d;
        bufA[p] = (j >= 0) ? Sp[i * TT + j] : 0.f;
    }
    for (int ib = dbase; ib < TT; ib += 2 * SPF) {
#pragma unroll
        for (int p = 0; p < SPF; p++) {
            int i = ib + SPF + p, j = i - d;
            bufB[p] = (i < TT && j >= 0) ? Sp[i * TT + j] : 0.f;
        }
#pragma unroll
        for (int p = 0; p < SPF; p++) {
            int i = ib + p;
            if (i >= d && i < TT) {
                float a = bufA[p];
                s += a;
                m = fmaxf(m, s * (1.f - a));
                Sp[i * TT + (i - d)] = s - m;
            }
        }
#pragma unroll
        for (int p = 0; p < SPF; p++) {
            int i = ib + 2 * SPF + p, j = i - d;
            bufA[p] = (i < TT && j >= 0) ? Sp[i * TT + j] : 0.f;
        }
#pragma unroll
        for (int p = 0; p < SPF; p++) {
            int i = ib + SPF + p;
            if (i >= d && i < TT) {
                float a = bufB[p];
                s += a;
                m = fmaxf(m, s * (1.f - a));
                Sp[i * TT + (i - d)] = s - m;
            }
        }
    }
}

// ---------------------------------------------------------------------------
// K5: fused causal softmax((scan + j/(i+1))/tau) + P@V, TWO-PASS,
// 64-row i-tiles (512 blocks -> good balance/occupancy).
// Thread (tx,ty) owns rows ty*4..+3, cols tx*4..+3. S is read directly from
// GMEM in both passes (coalesced: 16 lanes x float4 = 256B per row), no Ss
// smem buffer, no online rescaling, no per-tile shuffles.
// grid (16, 32), block 256, static smem 34.8 KB.
// ---------------------------------------------------------------------------
__global__ __launch_bounds__(256) void k_pvsm() {
    __shared__ float Vs[64][68];   // V tile [j][d]
    __shared__ float Ps[64][68];   // probs [row][j]
    int it = blockIdx.x, bh = blockIdx.y;
    int b = bh >> 3, h = bh & 7;
    const float* __restrict__ Sp = &g_S[bh][0][0];
    const float* __restrict__ V = &g_qkv[2][b * TT][h * DH];
    int tid = threadIdx.x;
    int tx = tid & 15, ty = tid >> 4;
    int i0 = it * 64;
    int nt = it + 1;               // number of 64-wide j tiles

    int gi[4];
    float invi[4], mx[4];
#pragma unroll
    for (int r = 0; r < 4; r++) {
        gi[r] = i0 + ty * 4 + r;
        invi[r] = 1.f / (float)(gi[r] + 1);
        mx[r] = -1e30f;
    }

    // ---- pass 1: row max (registers only) ----
    for (int jt = 0; jt < nt; jt++) {
        int jb = jt * 64 + tx * 4;
#pragma unroll
        for (int r = 0; r < 4; r++) {
            float4 s4 = *(const float4*)&Sp[gi[r] * TT + jb];
            float l0 = (jb + 0 <= gi[r]) ? s4.x + (float)(jb + 0) * invi[r] : -1e30f;
            float l1 = (jb + 1 <= gi[r]) ? s4.y + (float)(jb + 1) * invi[r] : -1e30f;
            float l2 = (jb + 2 <= gi[r]) ? s4.z + (float)(jb + 2) * invi[r] : -1e30f;
            float l3 = (jb + 3 <= gi[r]) ? s4.w + (float)(jb + 3) * invi[r] : -1e30f;
            mx[r] = fmaxf(mx[r], fmaxf(fmaxf(l0, l1), fmaxf(l2, l3)));
        }
    }
#pragma unroll
    for (int r = 0; r < 4; r++)
#pragma unroll
        for (int o = 8; o > 0; o >>= 1)
            mx[r] = fmaxf(mx[r], __shfl_xor_sync(0xffffffffu, mx[r], o));

    // ---- pass 2: exp + PV (ssum deferred) ----
    float acc[4][4], ssum[4];
#pragma unroll
    for (int r = 0; r < 4; r++) {
        ssum[r] = 0.f;
#pragma unroll
        for (int c = 0; c < 4; c++) acc[r][c] = 0.f;
    }

    for (int jt = 0; jt < nt; jt++) {
        int j0 = jt * 64;
        // cooperative V tile load (64 rows x 64 cols)
#pragma unroll
        for (int l = 0; l < 4; l++) {
            int row = ty + l * 16;
            *(float4*)&Vs[row][tx * 4] = *(const float4*)&V[(j0 + row) * DDIM + tx * 4];
        }
        // probs for this thread's 4 rows x 4 cols, straight from GMEM
#pragma unroll
        for (int r = 0; r < 4; r++) {
            int jb = j0 + tx * 4;
            float4 s4 = *(const float4*)&Sp[gi[r] * TT + jb];
            float p0 = (jb + 0 <= gi[r]) ? __expf((s4.x + (float)(jb + 0) * invi[r] - mx[r]) * INV_TAU) : 0.f;
            float p1 = (jb + 1 <= gi[r]) ? __expf((s4.y + (float)(jb + 1) * invi[r] - mx[r]) * INV_TAU) : 0.f;
            float p2 = (jb + 2 <= gi[r]) ? __expf((s4.z + (float)(jb + 2) * invi[r] - mx[r]) * INV_TAU) : 0.f;
            float p3 = (jb + 3 <= gi[r]) ? __expf((s4.w + (float)(jb + 3) * invi[r] - mx[r]) * INV_TAU) : 0.f;
            ssum[r] += p0 + p1 + p2 + p3;
            float4 p4 = {p0, p1, p2, p3};
            *(float4*)&Ps[ty * 4 + r][tx * 4] = p4;
        }
        __syncthreads();
        // MAC: acc[r][c] += sum_k Ps[row][k] * Vs[k][col]
#pragma unroll 4
        for (int k4 = 0; k4 < 64; k4 += 4) {
            float4 b0 = *(float4*)&Vs[k4 + 0][tx * 4];
            float4 b1 = *(float4*)&Vs[k4 + 1][tx * 4];
            float4 b2 = *(float4*)&Vs[k4 + 2][tx * 4];
            float4 b3 = *(float4*)&Vs[k4 + 3][tx * 4];
#pragma unroll
            for (int r = 0; r < 4; r++) {
                float4 a = *(float4*)&Ps[ty * 4 + r][k4];
                acc[r][0] += a.x * b0.x + a.y * b1.x + a.z * b2.x + a.w * b3.x;
                acc[r][1] += a.x * b0.y + a.y * b1.y + a.z * b2.y + a.w * b3.y;
                acc[r][2] += a.x * b0.z + a.y * b1.z + a.z * b2.z + a.w * b3.z;
                acc[r][3] += a.x * b0.w + a.y * b1.w + a.z * b2.w + a.w * b3.w;
            }
        }
        __syncthreads();
    }
#pragma unroll
    for (int r = 0; r < 4; r++) {
#pragma unroll
        for (int o = 8; o > 0; o >>= 1)
            ssum[r] += __shfl_xor_sync(0xffffffffu, ssum[r], o);
        float inv = 1.f / ssum[r];
        float4 o4 = {acc[r][0] * inv, acc[r][1] * inv, acc[r][2] * inv, acc[r][3] * inv};
        *(float4*)&g_O[bh][gi[r]][tx * 4] = o4;
    }
}

// ---------------------------------------------------------------------------
// K7: out[b,t,h*64+e] = sum_d O[bh][t][d] * wo[h*64+d][e]. K=64, N=64.
// grid (16, 32), block 256.
// ---------------------------------------------------------------------------
__global__ __launch_bounds__(256) void k_out(const float* __restrict__ wo,
                                             float* __restrict__ out) {
    int it = blockIdx.x, bh = blockIdx.y;
    int b = bh >> 3, h = bh & 7;
    __shared__ float Os[DH][68];
    __shared__ float Ws[DH][68];
    int tid = threadIdx.x;
    int lrow = tid >> 4, lcol = (tid & 15) * 4;
#pragma unroll
    for (int l = 0; l < 4; l++) {
        int row = lrow + l * 16;
        float4 o4 = *(const float4*)&g_O[bh][it * 64 + row][lcol];
        Os[lcol + 0][row] = o4.x; Os[lcol + 1][row] = o4.y;
        Os[lcol + 2][row] = o4.z; Os[lcol + 3][row] = o4.w;
        float4 w4 = *(const float4*)&wo[(h * 64 + row) * 64 + lcol];
        *(float4*)&Ws[row][lcol] = w4;
    }
    __syncthreads();
    int tx = tid & 15, ty = tid >> 4;
    float acc[4][4];
#pragma unroll
    for (int r = 0; r < 4; r++)
#pragma unroll
        for (int c = 0; c < 4; c++) acc[r][c] = 0.f;
#pragma unroll 8
    for (int k = 0; k < 64; k++) {
        float4 a4 = *(const float4*)&Os[k][ty * 4];
        float4 b4 = *(const float4*)&Ws[k][tx * 4];
        float a[4] = {a4.x, a4.y, a4.z, a4.w};
        float bb[4] = {b4.x, b4.y, b4.z, b4.w};
#pragma unroll
        for (int r = 0; r < 4; r++)
#pragma unroll
            for (int c = 0; c < 4; c++) acc[r][c] += a[r] * bb[c];
    }
#pragma unroll
    for (int r = 0; r < 4; r++) {
        int t = it * 64 + ty * 4 + r;
        float4 o4 = {acc[r][0], acc[r][1], acc[r][2], acc[r][3]};
        *(float4*)&out[(b * TT + t) * DDIM + h * 64 + tx * 4] = o4;
    }
}

// ---------------------------------------------------------------------------
extern "C" void kernel_launch(void* const* d_in, const int* in_sizes, int n_in,
                              void* d_out, int out_size) {
    const float* x  = (const float*)d_in[0];
    const float* wq = (const float*)d_in[1];
    const float* wk = (const float*)d_in[2];
    const float* wv = (const float*)d_in[3];
    const float* wo = (const float*)d_in[4];
    float* out = (float*)d_out;

    k_qkv<<<dim3(4, 32, 3), 256>>>(x, wq, wk, wv);
    k_score<<<dim3(8, 8, 32), 256>>>();
    k_scan<<<dim3(8, 32), 128>>>();
    k_pvsm<<<dim3(16, 32), 256>>>();
    k_out<<<dim3(16, 32), 256>>>(wo, out);
}

// round 8
// speedup vs baseline: 1.2702x; 1.1498x over previous
#include <cuda_runtime.h>

// Fixed problem shapes
#define BSZ  4
#define TT   1024
#define DDIM 512
#define HH   8
#define DH   64
#define MROWS (BSZ*TT)   // 4096
#define NBH   (BSZ*HH)   // 32
#define INV_TAU 10.0f

// Scratch (device globals: allocation-free)
__device__ __align__(128) float g_qkv[3][MROWS][DDIM];   // 25 MB: q,k,v post-softmax
__device__ __align__(128) float g_S[NBH][TT][TT];        // 134 MB: scores -> scan

// ---------------------------------------------------------------------------
// K1: QKV projections WITH fused per-head softmax(x/tau) epilogue.
// 128x128 tile, BK=16, A/B double-buffered smem (ONE sync per k-iter),
// 8x8 per thread, 256 threads. grid (4, 32, 3).
// ---------------------------------------------------------------------------
__global__ __launch_bounds__(256) void k_qkv(const float* __restrict__ X,
                                             const float* __restrict__ Wq,
                                             const float* __restrict__ Wk,
                                             const float* __restrict__ Wv) {
    const float* W = (blockIdx.z == 0) ? Wq : ((blockIdx.z == 1) ? Wk : Wv);
    float* Out = &g_qkv[blockIdx.z][0][0];
    __shared__ float As[2][16][128];
    __shared__ float Bs[2][16][128];
    int tid = threadIdx.x;
    int m0 = blockIdx.y * 128, n0 = blockIdx.x * 128;
    int ar = tid >> 1, ac = (tid & 1) * 8;       // A: row 0..127, col group 0/8
    int br = tid >> 4, bc = (tid & 15) * 8;      // B: row 0..15, col group *8
    int tx = tid & 15, ty = tid >> 4;
    float acc[8][8];
#pragma unroll
    for (int r = 0; r < 8; r++)
#pragma unroll
        for (int c = 0; c < 8; c++) acc[r][c] = 0.f;

    // preload tile 0
    float4 a0 = *(const float4*)&X[(m0 + ar) * DDIM + ac];
    float4 a1 = *(const float4*)&X[(m0 + ar) * DDIM + ac + 4];
    float4 b0 = *(const float4*)&W[br * DDIM + n0 + bc];
    float4 b1 = *(const float4*)&W[br * DDIM + n0 + bc + 4];
    As[0][ac + 0][ar] = a0.x; As[0][ac + 1][ar] = a0.y;
    As[0][ac + 2][ar] = a0.z; As[0][ac + 3][ar] = a0.w;
    As[0][ac + 4][ar] = a1.x; As[0][ac + 5][ar] = a1.y;
    As[0][ac + 6][ar] = a1.z; As[0][ac + 7][ar] = a1.w;
    *(float4*)&Bs[0][br][bc]     = b0;
    *(float4*)&Bs[0][br][bc + 4] = b1;
    __syncthreads();

    int cur = 0;
    for (int k0 = 0; k0 < DDIM; k0 += 16) {
        int nk = k0 + 16;
        if (nk < DDIM) {
            a0 = *(const float4*)&X[(m0 + ar) * DDIM + nk + ac];
            a1 = *(const float4*)&X[(m0 + ar) * DDIM + nk + ac + 4];
            b0 = *(const float4*)&W[(nk + br) * DDIM + n0 + bc];
            b1 = *(const float4*)&W[(nk + br) * DDIM + n0 + bc + 4];
        }
#pragma unroll
        for (int k = 0; k < 16; k++) {
            float a[8], b[8];
            *(float4*)&a[0] = *(const float4*)&As[cur][k][ty * 8];
            *(float4*)&a[4] = *(const float4*)&As[cur][k][ty * 8 + 4];
            *(float4*)&b[0] = *(const float4*)&Bs[cur][k][tx * 8];
            *(float4*)&b[4] = *(const float4*)&Bs[cur][k][tx * 8 + 4];
#pragma unroll
            for (int r = 0; r < 8; r++)
#pragma unroll
                for (int c = 0; c < 8; c++) acc[r][c] += a[r] * b[c];
        }
        if (nk < DDIM) {
            int nxt = cur ^ 1;
            As[nxt][ac + 0][ar] = a0.x; As[nxt][ac + 1][ar] = a0.y;
            As[nxt][ac + 2][ar] = a0.z; As[nxt][ac + 3][ar] = a0.w;
            As[nxt][ac + 4][ar] = a1.x; As[nxt][ac + 5][ar] = a1.y;
            As[nxt][ac + 6][ar] = a1.z; As[nxt][ac + 7][ar] = a1.w;
            *(float4*)&Bs[nxt][br][bc]     = b0;
            *(float4*)&Bs[nxt][br][bc + 4] = b1;
            __syncthreads();
            cur = nxt;
        }
    }

    // fused softmax over each head's 64 cols (8 cols local x 8 lanes)
#pragma unroll
    for (int r = 0; r < 8; r++) {
        float mx = acc[r][0];
#pragma unroll
        for (int c = 1; c < 8; c++) mx = fmaxf(mx, acc[r][c]);
#pragma unroll
        for (int o = 4; o > 0; o >>= 1) mx = fmaxf(mx, __shfl_xor_sync(0xffffffffu, mx, o));
        float s = 0.f;
#pragma unroll
        for (int c = 0; c < 8; c++) {
            acc[r][c] = __expf((acc[r][c] - mx) * INV_TAU);
            s += acc[r][c];
        }
#pragma unroll
        for (int o = 4; o > 0; o >>= 1) s += __shfl_xor_sync(0xffffffffu, s, o);
        float inv = 1.f / s;
#pragma unroll
        for (int c = 0; c < 8; c++) acc[r][c] *= inv;
    }
#pragma unroll
    for (int r = 0; r < 8; r++) {
        int row = m0 + ty * 8 + r;
        *(float4*)&Out[row * DDIM + n0 + tx * 8]     = *(float4*)&acc[r][0];
        *(float4*)&Out[row * DDIM + n0 + tx * 8 + 4] = *(float4*)&acc[r][4];
    }
}

// ---------------------------------------------------------------------------
// K3: S = q_sm·k_smT, causal 128x128 tiles, BK=32, 8x8/thread.
// grid (8, 8, 32), block 256.
// ---------------------------------------------------------------------------
__global__ __launch_bounds__(256) void k_score() {
    int jt = blockIdx.x, it = blockIdx.y, bh = blockIdx.z;
    if (jt > it) return;
    int b = bh >> 3, h = bh & 7;
    const float* Q  = &g_qkv[0][b * TT][h * DH];
    const float* Kp = &g_qkv[1][b * TT][h * DH];
    __shared__ float Qs[32][132];
    __shared__ float Ks[32][132];
    int tid = threadIdx.x;
    int tx = tid & 15, ty = tid >> 4;
    float acc[8][8];
#pragma unroll
    for (int r = 0; r < 8; r++)
#pragma unroll
        for (int c = 0; c < 8; c++) acc[r][c] = 0.f;

    for (int k0 = 0; k0 < DH; k0 += 32) {
        __syncthreads();
#pragma unroll
        for (int l = 0; l < 4; l++) {
            int idx = tid + l * 256;
            int row = idx >> 3, cg = (idx & 7) * 4;
            float4 q4 = *(const float4*)&Q[(it * 128 + row) * DDIM + k0 + cg];
            float4 k4 = *(const float4*)&Kp[(jt * 128 + row) * DDIM + k0 + cg];
            Qs[cg + 0][row] = q4.x; Qs[cg + 1][row] = q4.y;
            Qs[cg + 2][row] = q4.z; Qs[cg + 3][row] = q4.w;
            Ks[cg + 0][row] = k4.x; Ks[cg + 1][row] = k4.y;
            Ks[cg + 2][row] = k4.z; Ks[cg + 3][row] = k4.w;
        }
        __syncthreads();
#pragma unroll
        for (int k = 0; k < 32; k++) {
            float a[8], bb[8];
            *(float4*)&a[0]  = *(const float4*)&Qs[k][ty * 8];
            *(float4*)&a[4]  = *(const float4*)&Qs[k][ty * 8 + 4];
            *(float4*)&bb[0] = *(const float4*)&Ks[k][tx * 8];
            *(float4*)&bb[4] = *(const float4*)&Ks[k][tx * 8 + 4];
#pragma unroll
            for (int r = 0; r < 8; r++)
#pragma unroll
                for (int c = 0; c < 8; c++) acc[r][c] += a[r] * bb[c];
        }
    }
    float* Sp = &g_S[bh][0][0];
#pragma unroll
    for (int r = 0; r < 8; r++) {
        int row = it * 128 + ty * 8 + r;
        *(float4*)&Sp[row * TT + jt * 128 + tx * 8]     = *(float4*)&acc[r][0];
        *(float4*)&Sp[row * TT + jt * 128 + tx * 8 + 4] = *(float4*)&acc[r][4];
    }
}

// ---------------------------------------------------------------------------
// K4: per-subdiagonal scan, in place on g_S. A/B double-buffered 32-row
// blocks. grid (8, 32), block 128.
// ---------------------------------------------------------------------------
#define SPF 32
__global__ __launch_bounds__(128) void k_scan() {
    int bh = blockIdx.y;
    int dbase = blockIdx.x * 128;
    int d = dbase + threadIdx.x;
    float* Sp = &g_S[bh][0][0];
    float bufA[SPF], bufB[SPF];
    float s = 0.f, m = 0.f;
#pragma unroll
    for (int p = 0; p < SPF; p++) {
        int i = dbase + p, j = i - d;
        bufA[p] = (j >= 0) ? Sp[i * TT + j] : 0.f;
    }
    for (int ib = dbase; ib < TT; ib += 2 * SPF) {
#pragma unroll
        for (int p = 0; p < SPF; p++) {
            int i = ib + SPF + p, j = i - d;
            bufB[p] = (i < TT && j >= 0) ? Sp[i * TT + j] : 0.f;
        }
#pragma unroll
        for (int p = 0; p < SPF; p++) {
            int i = ib + p;
            if (i >= d && i < TT) {
                float a = bufA[p];
                s += a;
                m = fmaxf(m, s * (1.f - a));
                Sp[i * TT + (i - d)] = s - m;
            }
        }
#pragma unroll
        for (int p = 0; p < SPF; p++) {
            int i = ib + 2 * SPF + p, j = i - d;
            bufA[p] = (i < TT && j >= 0) ? Sp[i * TT + j] : 0.f;
        }
#pragma unroll
        for (int p = 0; p < SPF; p++) {
            int i = ib + SPF + p;
            if (i >= d && i < TT) {
                float a = bufB[p];
                s += a;
                m = fmaxf(m, s * (1.f - a));
                Sp[i * TT + (i - d)] = s - m;
            }
        }
    }
}

// ---------------------------------------------------------------------------
// K5: fused causal softmax((scan + j/(i+1))/tau) + P@V + output projection.
// R5 online-softmax flash structure (the 110.6us variant), plus an epilogue
// that multiplies the normalized 64xDh O-tile by wo[h] (64x64) in smem and
// writes straight to the harness output -- k_out and g_O are gone.
// grid (16, 32), block 256.
// ---------------------------------------------------------------------------
__global__ __launch_bounds__(256) void k_pvsm(const float* __restrict__ wo,
                                              float* __restrict__ out) {
    int it = blockIdx.x, bh = blockIdx.y;
    int b = bh >> 3, h = bh & 7;
    const float* Sp = &g_S[bh][0][0];
    const float* V = &g_qkv[2][b * TT][h * DH];
    __shared__ float Ss[64][68];   // logits tile [row][j]
    __shared__ float Vs[64][68];   // V tile [j][d] (reused for wo in epilogue)
    __shared__ float Ps[64][68];   // probs [row][j] (reused for O in epilogue)
    int tid = threadIdx.x;
    int tx = tid & 15, ty = tid >> 4;
    int i0 = it * 64;

    float acc[4][4], m[4], ssum[4], invi[4];
#pragma unroll
    for (int r = 0; r < 4; r++) {
        m[r] = -1e30f; ssum[r] = 0.f;
        invi[r] = 1.f / (float)(i0 + ty * 4 + r + 1);
#pragma unroll
        for (int c = 0; c < 4; c++) acc[r][c] = 0.f;
    }

    for (int jt = 0; jt <= it; jt++) {
        int j0 = jt * 64;
#pragma unroll
        for (int l = 0; l < 4; l++) {
            int row = ty + l * 16;
            *(float4*)&Ss[row][tx * 4] = *(const float4*)&Sp[(i0 + row) * TT + j0 + tx * 4];
            *(float4*)&Vs[row][tx * 4] = *(const float4*)&V[(j0 + row) * DDIM + tx * 4];
        }
        __syncthreads();

#pragma unroll
        for (int r = 0; r < 4; r++) {
            int gi = i0 + ty * 4 + r;
            float4 s4 = *(float4*)&Ss[ty * 4 + r][tx * 4];
            float pr[4];
            int jb = j0 + tx * 4;
            pr[0] = (jb + 0 <= gi) ? s4.x + (float)(jb + 0) * invi[r] : -1e30f;
            pr[1] = (jb + 1 <= gi) ? s4.y + (float)(jb + 1) * invi[r] : -1e30f;
            pr[2] = (jb + 2 <= gi) ? s4.z + (float)(jb + 2) * invi[r] : -1e30f;
            pr[3] = (jb + 3 <= gi) ? s4.w + (float)(jb + 3) * invi[r] : -1e30f;
            float lmx = fmaxf(fmaxf(pr[0], pr[1]), fmaxf(pr[2], pr[3]));
#pragma unroll
            for (int o = 8; o > 0; o >>= 1)
                lmx = fmaxf(lmx, __shfl_xor_sync(0xffffffffu, lmx, o));
            float nm = fmaxf(m[r], lmx);
            float scale = __expf((m[r] - nm) * INV_TAU);
            m[r] = nm;
            float ts = 0.f;
#pragma unroll
            for (int c = 0; c < 4; c++) {
                float e = __expf((pr[c] - nm) * INV_TAU);
                pr[c] = e;
                ts += e;
            }
#pragma unroll
            for (int o = 8; o > 0; o >>= 1)
                ts += __shfl_xor_sync(0xffffffffu, ts, o);
            ssum[r] = ssum[r] * scale + ts;
#pragma unroll
            for (int c = 0; c < 4; c++) acc[r][c] *= scale;
            float4 p4 = {pr[0], pr[1], pr[2], pr[3]};
            *(float4*)&Ps[ty * 4 + r][tx * 4] = p4;
        }
        __syncthreads();

#pragma unroll 8
        for (int k4 = 0; k4 < 64; k4 += 4) {
            float4 a0 = *(float4*)&Ps[ty * 4 + 0][k4];
            float4 a1 = *(float4*)&Ps[ty * 4 + 1][k4];
            float4 a2 = *(float4*)&Ps[ty * 4 + 2][k4];
            float4 a3 = *(float4*)&Ps[ty * 4 + 3][k4];
            float4 b0 = *(float4*)&Vs[k4 + 0][tx * 4];
            float4 b1 = *(float4*)&Vs[k4 + 1][tx * 4];
            float4 b2 = *(float4*)&Vs[k4 + 2][tx * 4];
            float4 b3 = *(float4*)&Vs[k4 + 3][tx * 4];
            float ar[4][4] = {{a0.x, a0.y, a0.z, a0.w},
                              {a1.x, a1.y, a1.z, a1.w},
                              {a2.x, a2.y, a2.z, a2.w},
                              {a3.x, a3.y, a3.z, a3.w}};
            float bb[4][4] = {{b0.x, b0.y, b0.z, b0.w},
                              {b1.x, b1.y, b1.z, b1.w},
                              {b2.x, b2.y, b2.z, b2.w},
                              {b3.x, b3.y, b3.z, b3.w}};
#pragma unroll
            for (int r = 0; r < 4; r++)
#pragma unroll
                for (int kk = 0; kk < 4; kk++)
#pragma unroll
                    for (int c = 0; c < 4; c++)
                        acc[r][c] += ar[r][kk] * bb[kk][c];
        }
        __syncthreads();
    }

    // ---- fused output projection: out_tile = O_tile(64xDh) @ wo_h(64x64) ----
    // normalized O -> Ps[row][d]; wo_h -> Vs[d][e]
#pragma unroll
    for (int r = 0; r < 4; r++) {
        float inv = 1.f / ssum[r];
        float4 o4 = {acc[r][0] * inv, acc[r][1] * inv, acc[r][2] * inv, acc[r][3] * inv};
        *(float4*)&Ps[ty * 4 + r][tx * 4] = o4;
    }
#pragma unroll
    for (int l = 0; l < 4; l++) {
        int row = ty + l * 16;
        *(float4*)&Vs[row][tx * 4] = *(const float4*)&wo[(h * 64 + row) * 64 + tx * 4];
    }
    __syncthreads();

    float acc2[4][4];
#pragma unroll
    for (int r = 0; r < 4; r++)
#pragma unroll
        for (int c = 0; c < 4; c++) acc2[r][c] = 0.f;
#pragma unroll 8
    for (int k4 = 0; k4 < 64; k4 += 4) {
        float4 b0 = *(float4*)&Vs[k4 + 0][tx * 4];
        float4 b1 = *(float4*)&Vs[k4 + 1][tx * 4];
        float4 b2 = *(float4*)&Vs[k4 + 2][tx * 4];
        float4 b3 = *(float4*)&Vs[k4 + 3][tx * 4];
#pragma unroll
        for (int r = 0; r < 4; r++) {
            float4 a = *(float4*)&Ps[ty * 4 + r][k4];
            acc2[r][0] += a.x * b0.x + a.y * b1.x + a.z * b2.x + a.w * b3.x;
            acc2[r][1] += a.x * b0.y + a.y * b1.y + a.z * b2.y + a.w * b3.y;
            acc2[r][2] += a.x * b0.z + a.y * b1.z + a.z * b2.z + a.w * b3.z;
            acc2[r][3] += a.x * b0.w + a.y * b1.w + a.z * b2.w + a.w * b3.w;
        }
    }
#pragma unroll
    for (int r = 0; r < 4; r++) {
        int t = i0 + ty * 4 + r;
        float4 o4 = {acc2[r][0], acc2[r][1], acc2[r][2], acc2[r][3]};
        *(float4*)&out[(b * TT + t) * DDIM + h * 64 + tx * 4] = o4;
    }
}

// ---------------------------------------------------------------------------
extern "C" void kernel_launch(void* const* d_in, const int* in_sizes, int n_in,
                              void* d_out, int out_size) {
    const float* x  = (const float*)d_in[0];
    const float* wq = (const float*)d_in[1];
    const float* wk = (const float*)d_in[2];
    const float* wv = (const float*)d_in[3];
    const float* wo = (const float*)d_in[4];
    float* out = (float*)d_out;

    k_qkv<<<dim3(4, 32, 3), 256>>>(x, wq, wk, wv);
    k_score<<<dim3(8, 8, 32), 256>>>();
    k_scan<<<dim3(8, 32), 128>>>();
    k_pvsm<<<dim3(16, 32), 256>>>(wo, out);
}

// round 9
// speedup vs baseline: 1.3845x; 1.0900x over previous
#include <cuda_runtime.h>

// Fixed problem shapes
#define BSZ  4
#define TT   1024
#define DDIM 512
#define HH   8
#define DH   64
#define MROWS (BSZ*TT)   // 4096
#define NBH   (BSZ*HH)   // 32
#define INV_TAU 10.0f

typedef unsigned long long u64;

// ---- packed f32x2 helpers (sm_103a FFMA2 path; pack/unpack on alu pipe) ----
__device__ __forceinline__ u64 pk2(float lo, float hi) {
    u64 o;
    asm("mov.b64 %0, {%1, %2};" : "=l"(o)
        : "r"(__float_as_uint(lo)), "r"(__float_as_uint(hi)));
    return o;
}
__device__ __forceinline__ u64 bcast2(float v) { return pk2(v, v); }
__device__ __forceinline__ void fma2(u64& d, u64 a, u64 b) {
    asm("fma.rn.f32x2 %0, %1, %2, %3;" : "=l"(d) : "l"(a), "l"(b), "l"(d));
}
__device__ __forceinline__ void mul2(u64& d, u64 a) {
    asm("mul.rn.f32x2 %0, %1, %2;" : "=l"(d) : "l"(d), "l"(a));
}
__device__ __forceinline__ void upk2(u64 v, float& lo, float& hi) {
    unsigned int x, y;
    asm("mov.b64 {%0, %1}, %2;" : "=r"(x), "=r"(y) : "l"(v));
    lo = __uint_as_float(x); hi = __uint_as_float(y);
}

// Scratch (device globals: allocation-free)
__device__ __align__(128) float g_qkv[3][MROWS][DDIM];   // 25 MB: q,k,v post-softmax
__device__ __align__(128) float g_S[NBH][TT][TT];        // 134 MB: scores -> scan

// ---------------------------------------------------------------------------
// K1: QKV projections + fused per-head softmax(x/tau) epilogue.
// 128x128 tile, BK=16, A/B double-buffered smem, 8x8/thread via FFMA2 pairs.
// grid (4, 32, 3), block 256.
// ---------------------------------------------------------------------------
__global__ __launch_bounds__(256) void k_qkv(const float* __restrict__ X,
                                             const float* __restrict__ Wq,
                                             const float* __restrict__ Wk,
                                             const float* __restrict__ Wv) {
    const float* W = (blockIdx.z == 0) ? Wq : ((blockIdx.z == 1) ? Wk : Wv);
    float* Out = &g_qkv[blockIdx.z][0][0];
    __shared__ float As[2][16][128];
    __shared__ float Bs[2][16][128];
    int tid = threadIdx.x;
    int m0 = blockIdx.y * 128, n0 = blockIdx.x * 128;
    int ar = tid >> 1, ac = (tid & 1) * 8;
    int br = tid >> 4, bc = (tid & 15) * 8;
    int tx = tid & 15, ty = tid >> 4;
    u64 acc2[8][4];
#pragma unroll
    for (int r = 0; r < 8; r++)
#pragma unroll
        for (int j = 0; j < 4; j++) acc2[r][j] = 0ull;

    // preload tile 0
    float4 a0 = *(const float4*)&X[(m0 + ar) * DDIM + ac];
    float4 a1 = *(const float4*)&X[(m0 + ar) * DDIM + ac + 4];
    float4 b0 = *(const float4*)&W[br * DDIM + n0 + bc];
    float4 b1 = *(const float4*)&W[br * DDIM + n0 + bc + 4];
    As[0][ac + 0][ar] = a0.x; As[0][ac + 1][ar] = a0.y;
    As[0][ac + 2][ar] = a0.z; As[0][ac + 3][ar] = a0.w;
    As[0][ac + 4][ar] = a1.x; As[0][ac + 5][ar] = a1.y;
    As[0][ac + 6][ar] = a1.z; As[0][ac + 7][ar] = a1.w;
    *(float4*)&Bs[0][br][bc]     = b0;
    *(float4*)&Bs[0][br][bc + 4] = b1;
    __syncthreads();

    int cur = 0;
    for (int k0 = 0; k0 < DDIM; k0 += 16) {
        int nk = k0 + 16;
        if (nk < DDIM) {
            a0 = *(const float4*)&X[(m0 + ar) * DDIM + nk + ac];
            a1 = *(const float4*)&X[(m0 + ar) * DDIM + nk + ac + 4];
            b0 = *(const float4*)&W[(nk + br) * DDIM + n0 + bc];
            b1 = *(const float4*)&W[(nk + br) * DDIM + n0 + bc + 4];
        }
#pragma unroll
        for (int k = 0; k < 16; k++) {
            float a[8], bb[8];
            *(float4*)&a[0]  = *(const float4*)&As[cur][k][ty * 8];
            *(float4*)&a[4]  = *(const float4*)&As[cur][k][ty * 8 + 4];
            *(float4*)&bb[0] = *(const float4*)&Bs[cur][k][tx * 8];
            *(float4*)&bb[4] = *(const float4*)&Bs[cur][k][tx * 8 + 4];
            u64 bp[4];
            bp[0] = pk2(bb[0], bb[1]); bp[1] = pk2(bb[2], bb[3]);
            bp[2] = pk2(bb[4], bb[5]); bp[3] = pk2(bb[6], bb[7]);
#pragma unroll
            for (int r = 0; r < 8; r++) {
                u64 ap = bcast2(a[r]);
#pragma unroll
                for (int j = 0; j < 4; j++) fma2(acc2[r][j], ap, bp[j]);
            }
        }
        if (nk < DDIM) {
            int nxt = cur ^ 1;
            As[nxt][ac + 0][ar] = a0.x; As[nxt][ac + 1][ar] = a0.y;
            As[nxt][ac + 2][ar] = a0.z; As[nxt][ac + 3][ar] = a0.w;
            As[nxt][ac + 4][ar] = a1.x; As[nxt][ac + 5][ar] = a1.y;
            As[nxt][ac + 6][ar] = a1.z; As[nxt][ac + 7][ar] = a1.w;
            *(float4*)&Bs[nxt][br][bc]     = b0;
            *(float4*)&Bs[nxt][br][bc + 4] = b1;
            __syncthreads();
            cur = nxt;
        }
    }

    float acc[8][8];
#pragma unroll
    for (int r = 0; r < 8; r++)
#pragma unroll
        for (int j = 0; j < 4; j++) upk2(acc2[r][j], acc[r][2 * j], acc[r][2 * j + 1]);

    // fused softmax over each head's 64 cols (8 cols local x 8 lanes)
#pragma unroll
    for (int r = 0; r < 8; r++) {
        float mx = acc[r][0];
#pragma unroll
        for (int c = 1; c < 8; c++) mx = fmaxf(mx, acc[r][c]);
#pragma unroll
        for (int o = 4; o > 0; o >>= 1) mx = fmaxf(mx, __shfl_xor_sync(0xffffffffu, mx, o));
        float s = 0.f;
#pragma unroll
        for (int c = 0; c < 8; c++) {
            acc[r][c] = __expf((acc[r][c] - mx) * INV_TAU);
            s += acc[r][c];
        }
#pragma unroll
        for (int o = 4; o > 0; o >>= 1) s += __shfl_xor_sync(0xffffffffu, s, o);
        float inv = 1.f / s;
#pragma unroll
        for (int c = 0; c < 8; c++) acc[r][c] *= inv;
    }
#pragma unroll
    for (int r = 0; r < 8; r++) {
        int row = m0 + ty * 8 + r;
        *(float4*)&Out[row * DDIM + n0 + tx * 8]     = *(float4*)&acc[r][0];
        *(float4*)&Out[row * DDIM + n0 + tx * 8 + 4] = *(float4*)&acc[r][4];
    }
}

// ---------------------------------------------------------------------------
// K3: S = q_sm·k_smT, causal 128x128 tiles, BK=32, 8x8/thread via FFMA2.
// grid (8, 8, 32), block 256.
// ---------------------------------------------------------------------------
__global__ __launch_bounds__(256) void k_score() {
    int jt = blockIdx.x, it = blockIdx.y, bh = blockIdx.z;
    if (jt > it) return;
    int b = bh >> 3, h = bh & 7;
    const float* Q  = &g_qkv[0][b * TT][h * DH];
    const float* Kp = &g_qkv[1][b * TT][h * DH];
    __shared__ float Qs[32][132];
    __shared__ float Ks[32][132];
    int tid = threadIdx.x;
    int tx = tid & 15, ty = tid >> 4;
    u64 acc2[8][4];
#pragma unroll
    for (int r = 0; r < 8; r++)
#pragma unroll
        for (int j = 0; j < 4; j++) acc2[r][j] = 0ull;

    for (int k0 = 0; k0 < DH; k0 += 32) {
        __syncthreads();
#pragma unroll
        for (int l = 0; l < 4; l++) {
            int idx = tid + l * 256;
            int row = idx >> 3, cg = (idx & 7) * 4;
            float4 q4 = *(const float4*)&Q[(it * 128 + row) * DDIM + k0 + cg];
            float4 k4 = *(const float4*)&Kp[(jt * 128 + row) * DDIM + k0 + cg];
            Qs[cg + 0][row] = q4.x; Qs[cg + 1][row] = q4.y;
            Qs[cg + 2][row] = q4.z; Qs[cg + 3][row] = q4.w;
            Ks[cg + 0][row] = k4.x; Ks[cg + 1][row] = k4.y;
            Ks[cg + 2][row] = k4.z; Ks[cg + 3][row] = k4.w;
        }
        __syncthreads();
#pragma unroll
        for (int k = 0; k < 32; k++) {
            float a[8], bb[8];
            *(float4*)&a[0]  = *(const float4*)&Qs[k][ty * 8];
            *(float4*)&a[4]  = *(const float4*)&Qs[k][ty * 8 + 4];
            *(float4*)&bb[0] = *(const float4*)&Ks[k][tx * 8];
            *(float4*)&bb[4] = *(const float4*)&Ks[k][tx * 8 + 4];
            u64 bp[4];
            bp[0] = pk2(bb[0], bb[1]); bp[1] = pk2(bb[2], bb[3]);
            bp[2] = pk2(bb[4], bb[5]); bp[3] = pk2(bb[6], bb[7]);
#pragma unroll
            for (int r = 0; r < 8; r++) {
                u64 ap = bcast2(a[r]);
#pragma unroll
                for (int j = 0; j < 4; j++) fma2(acc2[r][j], ap, bp[j]);
            }
        }
    }
    float* Sp = &g_S[bh][0][0];
#pragma unroll
    for (int r = 0; r < 8; r++) {
        float acc[8];
#pragma unroll
        for (int j = 0; j < 4; j++) upk2(acc2[r][j], acc[2 * j], acc[2 * j + 1]);
        int row = it * 128 + ty * 8 + r;
        *(float4*)&Sp[row * TT + jt * 128 + tx * 8]     = *(float4*)&acc[0];
        *(float4*)&Sp[row * TT + jt * 128 + tx * 8 + 4] = *(float4*)&acc[4];
    }
}

// ---------------------------------------------------------------------------
// K4: per-subdiagonal scan, in place on g_S. A/B double-buffered 32-row
// blocks. 1D grid, longest blocks first (dchunk = bid>>5 ascending => heavy
// d-ranges land in wave 1). grid 256, block 128.
// ---------------------------------------------------------------------------
#define SPF 32
__global__ __launch_bounds__(128) void k_scan() {
    int bid = blockIdx.x;
    int bh = bid & 31;
    int dbase = (bid >> 5) * 128;
    int d = dbase + threadIdx.x;
    float* Sp = &g_S[bh][0][0];
    float bufA[SPF], bufB[SPF];
    float s = 0.f, m = 0.f;
#pragma unroll
    for (int p = 0; p < SPF; p++) {
        int i = dbase + p, j = i - d;
        bufA[p] = (j >= 0) ? Sp[i * TT + j] : 0.f;
    }
    for (int ib = dbase; ib < TT; ib += 2 * SPF) {
#pragma unroll
        for (int p = 0; p < SPF; p++) {
            int i = ib + SPF + p, j = i - d;
            bufB[p] = (i < TT && j >= 0) ? Sp[i * TT + j] : 0.f;
        }
#pragma unroll
        for (int p = 0; p < SPF; p++) {
            int i = ib + p;
            if (i >= d && i < TT) {
                float a = bufA[p];
                s += a;
                m = fmaxf(m, s * (1.f - a));
                Sp[i * TT + (i - d)] = s - m;
            }
        }
#pragma unroll
        for (int p = 0; p < SPF; p++) {
            int i = ib + 2 * SPF + p, j = i - d;
            bufA[p] = (i < TT && j >= 0) ? Sp[i * TT + j] : 0.f;
        }
#pragma unroll
        for (int p = 0; p < SPF; p++) {
            int i = ib + SPF + p;
            if (i >= d && i < TT) {
                float a = bufB[p];
                s += a;
                m = fmaxf(m, s * (1.f - a));
                Sp[i * TT + (i - d)] = s - m;
            }
        }
    }
}

// ---------------------------------------------------------------------------
// K5: fused causal softmax((scan + j/(i+1))/tau) + P@V + output projection.
// Online-softmax flash structure, FFMA2 MACs. grid (16, 32), block 256.
// ---------------------------------------------------------------------------
__global__ __launch_bounds__(256) void k_pvsm(const float* __restrict__ wo,
                                              float* __restrict__ out) {
    int it = blockIdx.x, bh = blockIdx.y;
    int b = bh >> 3, h = bh & 7;
    const float* Sp = &g_S[bh][0][0];
    const float* V = &g_qkv[2][b * TT][h * DH];
    __shared__ float Ss[64][68];   // logits tile [row][j]
    __shared__ float Vs[64][68];   // V tile [j][d] (reused for wo in epilogue)
    __shared__ float Ps[64][68];   // probs [row][j] (reused for O in epilogue)
    int tid = threadIdx.x;
    int tx = tid & 15, ty = tid >> 4;
    int i0 = it * 64;

    u64 acc2[4][2];
    float m[4], ssum[4], invi[4];
#pragma unroll
    for (int r = 0; r < 4; r++) {
        m[r] = -1e30f; ssum[r] = 0.f;
        invi[r] = 1.f / (float)(i0 + ty * 4 + r + 1);
        acc2[r][0] = 0ull; acc2[r][1] = 0ull;
    }

    for (int jt = 0; jt <= it; jt++) {
        int j0 = jt * 64;
#pragma unroll
        for (int l = 0; l < 4; l++) {
            int row = ty + l * 16;
            *(float4*)&Ss[row][tx * 4] = *(const float4*)&Sp[(i0 + row) * TT + j0 + tx * 4];
            *(float4*)&Vs[row][tx * 4] = *(const float4*)&V[(j0 + row) * DDIM + tx * 4];
        }
        __syncthreads();

#pragma unroll
        for (int r = 0; r < 4; r++) {
            int gi = i0 + ty * 4 + r;
            float4 s4 = *(float4*)&Ss[ty * 4 + r][tx * 4];
            float pr[4];
            int jb = j0 + tx * 4;
            pr[0] = (jb + 0 <= gi) ? s4.x + (float)(jb + 0) * invi[r] : -1e30f;
            pr[1] = (jb + 1 <= gi) ? s4.y + (float)(jb + 1) * invi[r] : -1e30f;
            pr[2] = (jb + 2 <= gi) ? s4.z + (float)(jb + 2) * invi[r] : -1e30f;
            pr[3] = (jb + 3 <= gi) ? s4.w + (float)(jb + 3) * invi[r] : -1e30f;
            float lmx = fmaxf(fmaxf(pr[0], pr[1]), fmaxf(pr[2], pr[3]));
#pragma unroll
            for (int o = 8; o > 0; o >>= 1)
                lmx = fmaxf(lmx, __shfl_xor_sync(0xffffffffu, lmx, o));
            float nm = fmaxf(m[r], lmx);
            float scale = __expf((m[r] - nm) * INV_TAU);
            m[r] = nm;
            float ts = 0.f;
#pragma unroll
            for (int c = 0; c < 4; c++) {
                float e = __expf((pr[c] - nm) * INV_TAU);
                pr[c] = e;
                ts += e;
            }
#pragma unroll
            for (int o = 8; o > 0; o >>= 1)
                ts += __shfl_xor_sync(0xffffffffu, ts, o);
            ssum[r] = ssum[r] * scale + ts;
            u64 sc = bcast2(scale);
            mul2(acc2[r][0], sc);
            mul2(acc2[r][1], sc);
            float4 p4 = {pr[0], pr[1], pr[2], pr[3]};
            *(float4*)&Ps[ty * 4 + r][tx * 4] = p4;
        }
        __syncthreads();

#pragma unroll 4
        for (int k4 = 0; k4 < 64; k4 += 4) {
            float4 b0 = *(float4*)&Vs[k4 + 0][tx * 4];
            float4 b1 = *(float4*)&Vs[k4 + 1][tx * 4];
            float4 b2 = *(float4*)&Vs[k4 + 2][tx * 4];
            float4 b3 = *(float4*)&Vs[k4 + 3][tx * 4];
            u64 bp00 = pk2(b0.x, b0.y), bp01 = pk2(b0.z, b0.w);
            u64 bp10 = pk2(b1.x, b1.y), bp11 = pk2(b1.z, b1.w);
            u64 bp20 = pk2(b2.x, b2.y), bp21 = pk2(b2.z, b2.w);
            u64 bp30 = pk2(b3.x, b3.y), bp31 = pk2(b3.z, b3.w);
#pragma unroll
            for (int r = 0; r < 4; r++) {
                float4 a = *(float4*)&Ps[ty * 4 + r][k4];
                u64 t;
                t = bcast2(a.x); fma2(acc2[r][0], t, bp00); fma2(acc2[r][1], t, bp01);
                t = bcast2(a.y); fma2(acc2[r][0], t, bp10); fma2(acc2[r][1], t, bp11);
                t = bcast2(a.z); fma2(acc2[r][0], t, bp20); fma2(acc2[r][1], t, bp21);
                t = bcast2(a.w); fma2(acc2[r][0], t, bp30); fma2(acc2[r][1], t, bp31);
            }
        }
        __syncthreads();
    }

    // ---- fused output projection: out = O(64xDh) @ wo_h(64x64) ----
#pragma unroll
    for (int r = 0; r < 4; r++) {
        float inv = 1.f / ssum[r];
        float a0, a1, a2, a3;
        upk2(acc2[r][0], a0, a1);
        upk2(acc2[r][1], a2, a3);
        float4 o4 = {a0 * inv, a1 * inv, a2 * inv, a3 * inv};
        *(float4*)&Ps[ty * 4 + r][tx * 4] = o4;
    }
#pragma unroll
    for (int l = 0; l < 4; l++) {
        int row = ty + l * 16;
        *(float4*)&Vs[row][tx * 4] = *(const float4*)&wo[(h * 64 + row) * 64 + tx * 4];
    }
    __syncthreads();

    u64 accb[4][2];
#pragma unroll
    for (int r = 0; r < 4; r++) { accb[r][0] = 0ull; accb[r][1] = 0ull; }
#pragma unroll 4
    for (int k4 = 0; k4 < 64; k4 += 4) {
        float4 b0 = *(float4*)&Vs[k4 + 0][tx * 4];
        float4 b1 = *(float4*)&Vs[k4 + 1][tx * 4];
        float4 b2 = *(float4*)&Vs[k4 + 2][tx * 4];
        float4 b3 = *(float4*)&Vs[k4 + 3][tx * 4];
        u64 bp00 = pk2(b0.x, b0.y), bp01 = pk2(b0.z, b0.w);
        u64 bp10 = pk2(b1.x, b1.y), bp11 = pk2(b1.z, b1.w);
        u64 bp20 = pk2(b2.x, b2.y), bp21 = pk2(b2.z, b2.w);
        u64 bp30 = pk2(b3.x, b3.y), bp31 = pk2(b3.z, b3.w);
#pragma unroll
        for (int r = 0; r < 4; r++) {
            float4 a = *(float4*)&Ps[ty * 4 + r][k4];
            u64 t;
            t = bcast2(a.x); fma2(accb[r][0], t, bp00); fma2(accb[r][1], t, bp01);
            t = bcast2(a.y); fma2(accb[r][0], t, bp10); fma2(accb[r][1], t, bp11);
            t = bcast2(a.z); fma2(accb[r][0], t, bp20); fma2(accb[r][1], t, bp21);
            t = bcast2(a.w); fma2(accb[r][0], t, bp30); fma2(accb[r][1], t, bp31);
        }
    }
#pragma unroll
    for (int r = 0; r < 4; r++) {
        int t = i0 + ty * 4 + r;
        float a0, a1, a2, a3;
        upk2(accb[r][0], a0, a1);
        upk2(accb[r][1], a2, a3);
        float4 o4 = {a0, a1, a2, a3};
        *(float4*)&out[(b * TT + t) * DDIM + h * 64 + tx * 4] = o4;
    }
}

// ---------------------------------------------------------------------------
extern "C" void kernel_launch(void* const* d_in, const int* in_sizes, int n_in,
                              void* d_out, int out_size) {
    const float* x  = (const float*)d_in[0];
    const float* wq = (const float*)d_in[1];
    const float* wk = (const float*)d_in[2];
    const float* wv = (const float*)d_in[3];
    const float* wo = (const float*)d_in[4];
    float* out = (float*)d_out;

    k_qkv<<<dim3(4, 32, 3), 256>>>(x, wq, wk, wv);
    k_score<<<dim3(8, 8, 32), 256>>>();
    k_scan<<<256, 128>>>();
    k_pvsm<<<dim3(16, 32), 256>>>(wo, out);
}